// round 13
// baseline (speedup 1.0000x reference)
#include <cuda_runtime.h>
#include <cuda_bf16.h>
#include <math_constants.h>
#include <cstdint>

#define NB 4096
#define NC 1000
#define ND 2048
#define CP 1024
#define TILE 64
#define NTILE (CP / TILE)                 // 16
#define NPAIRS (NTILE * (NTILE + 1) / 2)  // 136
#define KC 64                             // k-chunk per smem stage
#define APITCH 72                         // smem row pitch in halves (144B: conflict-free ldmatrix)
#define NARG (NB / 8)                     // 512 argmax blocks (8 rows each, warp-per-row)

// Scratch (device globals — no allocation allowed)
__device__ __align__(16) __nv_bfloat16 g_Wbf[CP * ND];  // 4MB bf16 copy of W (zero-padded rows)
__device__ float g_rdist[CP * CP];  // 1/(k*dist[i,j]); only i,j < NC meaningful
__device__ float g_sq[CP];          // row norms of bf16-rounded W
__device__ float g_ymax[NB];
__device__ int   g_j0[NB];

// ---------------------------------------------------------------------------
// PTX helpers
// ---------------------------------------------------------------------------
__device__ __forceinline__ void ldsm_x4(uint32_t &r0, uint32_t &r1, uint32_t &r2, uint32_t &r3,
                                        uint32_t addr) {
    asm volatile("ldmatrix.sync.aligned.m8n8.x4.shared.b16 {%0,%1,%2,%3}, [%4];"
                 : "=r"(r0), "=r"(r1), "=r"(r2), "=r"(r3) : "r"(addr));
}

__device__ __forceinline__ void mma16816(float *c, uint32_t a0, uint32_t a1, uint32_t a2,
                                         uint32_t a3, uint32_t b0, uint32_t b1) {
    asm volatile(
        "mma.sync.aligned.m16n8k16.row.col.f32.bf16.bf16.f32 "
        "{%0,%1,%2,%3}, {%4,%5,%6,%7}, {%8,%9}, {%0,%1,%2,%3};"
        : "+f"(c[0]), "+f"(c[1]), "+f"(c[2]), "+f"(c[3])
        : "r"(a0), "r"(a1), "r"(a2), "r"(a3), "r"(b0), "r"(b1));
}

// ---------------------------------------------------------------------------
// Kernel 1: convert W -> bf16 (zero-pad rows NC..CP) + row norms of rounded W.
// 2 rows per block (warps 0-3 row A, warps 4-7 row B); 4 coalesced float4
// loads in flight per thread.
// ---------------------------------------------------------------------------
__global__ void __launch_bounds__(256) convert_kernel(const float* __restrict__ W) {
    int tid = threadIdx.x;
    int half = tid >> 7;            // 0/1 -> which row of the pair
    int wg_tid = tid & 127;
    int lane = tid & 31;
    int w = tid >> 5;

    int row = blockIdx.x * 2 + half;
    float s = 0.f;

    if (row < NC) {
        const float4* src = (const float4*)(W + (long)row * ND);
        uint2* dst = (uint2*)(g_Wbf + (long)row * ND);
        float4 v[4];
        #pragma unroll
        for (int it = 0; it < 4; it++) v[it] = src[it * 128 + wg_tid];
        #pragma unroll
        for (int it = 0; it < 4; it++) {
            union { uint2 u; __nv_bfloat16 h[4]; } pk;
            pk.h[0] = __float2bfloat16_rn(v[it].x);
            pk.h[1] = __float2bfloat16_rn(v[it].y);
            pk.h[2] = __float2bfloat16_rn(v[it].z);
            pk.h[3] = __float2bfloat16_rn(v[it].w);
            #pragma unroll
            for (int i = 0; i < 4; i++) {
                float f = __bfloat162float(pk.h[i]);
                s += f * f;
            }
            dst[it * 128 + wg_tid] = pk.u;
        }
    } else {
        uint2* dst = (uint2*)(g_Wbf + (long)row * ND);
        #pragma unroll
        for (int it = 0; it < 4; it++) dst[it * 128 + wg_tid] = make_uint2(0, 0);
    }

    for (int o = 16; o > 0; o >>= 1) s += __shfl_down_sync(0xFFFFFFFFu, s, o);
    __shared__ float sm[8];
    if (lane == 0) sm[w] = s;
    __syncthreads();
    if (wg_tid == 0) {
        float t = sm[half * 4] + sm[half * 4 + 1] + sm[half * 4 + 2] + sm[half * 4 + 3];
        g_sq[row] = t;
    }
}

// ---------------------------------------------------------------------------
// Kernel 2 (FAT): blocks [0, NPAIRS)          -> triangular Gram + rdist epilogue
//                 blocks [NPAIRS, NPAIRS+NARG) -> argmax of prediction (warp/row)
// The argmax DRAM traffic overlaps the gram's tensor work and warms L2 for K3.
// ---------------------------------------------------------------------------
__global__ void __launch_bounds__(256) gram_argmax_kernel(const float* __restrict__ Kin,
                                                          const float* __restrict__ pred) {
    int tid = threadIdx.x;
    int wid = tid >> 5, lane = tid & 31;

    if (blockIdx.x >= NPAIRS) {
        // ---------------- argmax branch: warp-per-row ----------------
        int b = (blockIdx.x - NPAIRS) * 8 + wid;
        const float4* pr = (const float4*)(pred + (long)b * NC);
        float best = -CUDART_INF_F;
        int bidx = NC;
        #pragma unroll
        for (int it = 0; it < 8; it++) {
            int idx = it * 32 + lane;
            if (idx < 250) {
                float4 v = pr[idx];
                int c = idx * 4;
                if (v.x > best) { best = v.x; bidx = c; }
                if (v.y > best) { best = v.y; bidx = c + 1; }
                if (v.z > best) { best = v.z; bidx = c + 2; }
                if (v.w > best) { best = v.w; bidx = c + 3; }
            }
        }
        #pragma unroll
        for (int o = 16; o > 0; o >>= 1) {
            float v2 = __shfl_down_sync(0xFFFFFFFFu, best, o);
            int   i2 = __shfl_down_sync(0xFFFFFFFFu, bidx, o);
            if (v2 > best || (v2 == best && i2 < bidx)) { best = v2; bidx = i2; }
        }
        if (lane == 0) { g_ymax[b] = best; g_j0[b] = bidx; }
        return;
    }

    // ---------------- gram branch ----------------
    int p = blockIdx.x;
    int ti = 0;
    while (p >= NTILE - ti) { p -= NTILE - ti; ti++; }
    int tj = ti + p;
    int rowA = ti * TILE, rowB = tj * TILE;

    __shared__ __align__(16) __nv_bfloat16 sA[2][TILE * APITCH];
    __shared__ __align__(16) __nv_bfloat16 sB[2][TILE * APITCH];

    int wr = wid & 3;        // 4 row-strips of 16
    int wc = wid >> 2;       // 2 col-strips of 32

    uint32_t sA0 = (uint32_t)__cvta_generic_to_shared(sA[0]);
    uint32_t sA1 = (uint32_t)__cvta_generic_to_shared(sA[1]);
    uint32_t sB0 = (uint32_t)__cvta_generic_to_shared(sB[0]);
    uint32_t sB1 = (uint32_t)__cvta_generic_to_shared(sB[1]);

    int arow = wr * 16 + (lane & 15);
    int acol = (lane >> 4) << 3;
    uint32_t aOff = (uint32_t)(arow * APITCH + acol) * 2u;
    int brow = wc * 32 + (lane & 7) + ((lane >> 4) << 3);
    int bcol = ((lane >> 3) & 1) << 3;
    uint32_t bOff = (uint32_t)(brow * APITCH + bcol) * 2u;

    int ldg_tile[4], ldg_row[4], ldg_sub[4];
    #pragma unroll
    for (int t = 0; t < 4; t++) {
        ldg_tile[t] = t >> 1;
        ldg_row[t]  = ((t & 1) << 5) + (tid >> 3);
        ldg_sub[t]  = tid & 7;
    }

    float acc[4][4] = {};
    uint4 fetch[4];

    #pragma unroll
    for (int t = 0; t < 4; t++) {
        const __nv_bfloat16* gp = g_Wbf +
            (long)((ldg_tile[t] ? rowB : rowA) + ldg_row[t]) * ND + ldg_sub[t] * 8;
        fetch[t] = *(const uint4*)gp;
    }
    #pragma unroll
    for (int t = 0; t < 4; t++) {
        __nv_bfloat16* dp = (ldg_tile[t] ? sB[0] : sA[0]) + ldg_row[t] * APITCH + ldg_sub[t] * 8;
        *(uint4*)dp = fetch[t];
    }
    __syncthreads();

    const int NSTAGE = ND / KC;  // 32
    for (int s = 0; s < NSTAGE; s++) {
        if (s + 1 < NSTAGE) {
            int k0 = (s + 1) * KC;
            #pragma unroll
            for (int t = 0; t < 4; t++) {
                const __nv_bfloat16* gp = g_Wbf +
                    (long)((ldg_tile[t] ? rowB : rowA) + ldg_row[t]) * ND + k0 + ldg_sub[t] * 8;
                fetch[t] = *(const uint4*)gp;
            }
        }

        int buf = s & 1;
        uint32_t aBase  = (buf ? sA1 : sA0) + aOff;
        uint32_t bBase0 = (buf ? sB1 : sB0) + bOff;
        uint32_t bBase1 = bBase0 + 16 * APITCH * 2;

        #pragma unroll
        for (int kk = 0; kk < 4; kk++) {
            uint32_t a0, a1, a2, a3;
            ldsm_x4(a0, a1, a2, a3, aBase + kk * 32);
            uint32_t b0, b1, b2, b3, b4, b5, b6, b7;
            ldsm_x4(b0, b1, b2, b3, bBase0 + kk * 32);
            ldsm_x4(b4, b5, b6, b7, bBase1 + kk * 32);
            mma16816(acc[0], a0, a1, a2, a3, b0, b1);
            mma16816(acc[1], a0, a1, a2, a3, b2, b3);
            mma16816(acc[2], a0, a1, a2, a3, b4, b5);
            mma16816(acc[3], a0, a1, a2, a3, b6, b7);
        }

        if (s + 1 < NSTAGE) {
            int nbuf = (s + 1) & 1;
            #pragma unroll
            for (int t = 0; t < 4; t++) {
                __nv_bfloat16* dp = (ldg_tile[t] ? sB[nbuf] : sA[nbuf]) +
                                    ldg_row[t] * APITCH + ldg_sub[t] * 8;
                *(uint4*)dp = fetch[t];
            }
        }
        __syncthreads();
    }

    // epilogue: reciprocal distances, symmetric write
    const float DS = (float)(1.0 / (double)0.224f);
    float invk = 1.0f / (Kin[0] * DS);

    int g = lane >> 2, tg = lane & 3;
    int gi0 = rowA + wr * 16 + g;
    int gi1 = gi0 + 8;
    float sqi0 = g_sq[gi0], sqi1 = g_sq[gi1];

    #pragma unroll
    for (int t = 0; t < 4; t++) {
        int gj = rowB + wc * 32 + t * 8 + tg * 2;
        float sqj0 = g_sq[gj], sqj1 = g_sq[gj + 1];
        float d2, rv;
        d2 = sqi0 + sqj0 - 2.f * acc[t][0];
        rv = rsqrtf(fmaxf(d2, 0.f)) * invk;
        g_rdist[gi0 * CP + gj] = rv;  g_rdist[gj * CP + gi0] = rv;
        d2 = sqi0 + sqj1 - 2.f * acc[t][1];
        rv = rsqrtf(fmaxf(d2, 0.f)) * invk;
        g_rdist[gi0 * CP + gj + 1] = rv;  g_rdist[(gj + 1) * CP + gi0] = rv;
        d2 = sqi1 + sqj0 - 2.f * acc[t][2];
        rv = rsqrtf(fmaxf(d2, 0.f)) * invk;
        g_rdist[gi1 * CP + gj] = rv;  g_rdist[gj * CP + gi1] = rv;
        d2 = sqi1 + sqj1 - 2.f * acc[t][3];
        rv = rsqrtf(fmaxf(d2, 0.f)) * invk;
        g_rdist[gi1 * CP + gj + 1] = rv;  g_rdist[(gj + 1) * CP + gi1] = rv;
    }
}

// ---------------------------------------------------------------------------
// Kernel 3: warp-per-row min-ratio, barrier-free.
//   out[b] = min_{c != j0} (ymax - pred[b,c]) * g_rdist[j0, c]
// pred is L2-resident from K2's argmax pass; rdist (4MB) L2-resident.
// ---------------------------------------------------------------------------
__global__ void __launch_bounds__(256) min_kernel(const float* __restrict__ pred,
                                                  float* __restrict__ out) {
    int b = blockIdx.x * 8 + (threadIdx.x >> 5);
    int lane = threadIdx.x & 31;

    int j0 = g_j0[b];
    float ym = g_ymax[b];
    const float4* pr = (const float4*)(pred + (long)b * NC);
    const float4* dr = (const float4*)(g_rdist + (long)j0 * CP);

    float mn = CUDART_INF_F;
    #pragma unroll
    for (int it = 0; it < 8; it++) {
        int idx = it * 32 + lane;
        if (idx < 250) {
            float4 p = pr[idx];
            float4 d = dr[idx];
            int c = idx * 4;
            float r0 = (c     == j0) ? CUDART_INF_F : (ym - p.x) * d.x;
            float r1 = (c + 1 == j0) ? CUDART_INF_F : (ym - p.y) * d.y;
            float r2 = (c + 2 == j0) ? CUDART_INF_F : (ym - p.z) * d.z;
            float r3 = (c + 3 == j0) ? CUDART_INF_F : (ym - p.w) * d.w;
            mn = fminf(mn, fminf(fminf(r0, r1), fminf(r2, r3)));
        }
    }
    #pragma unroll
    for (int o = 16; o > 0; o >>= 1)
        mn = fminf(mn, __shfl_down_sync(0xFFFFFFFFu, mn, o));
    if (lane == 0) out[b] = mn;
}

// ---------------------------------------------------------------------------
extern "C" void kernel_launch(void* const* d_in, const int* in_sizes, int n_in,
                              void* d_out, int out_size) {
    const float* pred = (const float*)d_in[0];
    const float* W    = (const float*)d_in[1];
    const float* K    = (const float*)d_in[2];
    float* out = (float*)d_out;

    convert_kernel<<<CP / 2, 256>>>(W);
    gram_argmax_kernel<<<NPAIRS + NARG, 256>>>(K, pred);
    min_kernel<<<NB / 8, 256>>>(pred, out);
}

// round 14
// speedup vs baseline: 1.1276x; 1.1276x over previous
#include <cuda_runtime.h>
#include <cuda_bf16.h>
#include <math_constants.h>
#include <cstdint>

#define NB 4096
#define NC 1000
#define ND 2048
#define CP 1024
#define TILE 64
#define NTILE (CP / TILE)                 // 16
#define NPAIRS (NTILE * (NTILE + 1) / 2)  // 136
#define KC 64
#define APITCH 72                         // smem row pitch in halves
#define GRIDN 296                         // 2 CTAs/SM on 148 SMs worst case (guaranteed resident)

// Scratch (device globals — no allocation allowed)
__device__ __align__(16) __nv_bfloat16 g_Wbf[CP * ND];  // 4MB bf16 copy of W (zero-padded rows)
__device__ float g_rdist[CP * CP];  // 1/(k*dist[i,j])
__device__ float g_sq[CP];          // row norms of bf16-rounded W
__device__ float g_ymax[NB];
__device__ int   g_j0[NB];
__device__ unsigned g_bar_count;    // zero-init; self-resetting
__device__ unsigned g_bar_gen;      // monotonic generation counter (replay-safe)

// ---------------------------------------------------------------------------
// Software grid barrier (all GRIDN blocks co-resident by construction).
// ---------------------------------------------------------------------------
__device__ __forceinline__ void grid_barrier() {
    __threadfence();          // every thread makes its writes device-visible
    __syncthreads();
    if (threadIdx.x == 0) {
        unsigned g0 = atomicAdd(&g_bar_gen, 0u);
        unsigned a = atomicAdd(&g_bar_count, 1u);
        if (a == GRIDN - 1u) {
            atomicExch(&g_bar_count, 0u);
            __threadfence();
            atomicExch(&g_bar_gen, g0 + 1u);
        } else {
            while (atomicAdd(&g_bar_gen, 0u) == g0) { __nanosleep(64); }
            __threadfence();
        }
    }
    __syncthreads();
}

// ---------------------------------------------------------------------------
// PTX helpers
// ---------------------------------------------------------------------------
__device__ __forceinline__ void ldsm_x4(uint32_t &r0, uint32_t &r1, uint32_t &r2, uint32_t &r3,
                                        uint32_t addr) {
    asm volatile("ldmatrix.sync.aligned.m8n8.x4.shared.b16 {%0,%1,%2,%3}, [%4];"
                 : "=r"(r0), "=r"(r1), "=r"(r2), "=r"(r3) : "r"(addr));
}

__device__ __forceinline__ void mma16816(float *c, uint32_t a0, uint32_t a1, uint32_t a2,
                                         uint32_t a3, uint32_t b0, uint32_t b1) {
    asm volatile(
        "mma.sync.aligned.m16n8k16.row.col.f32.bf16.bf16.f32 "
        "{%0,%1,%2,%3}, {%4,%5,%6,%7}, {%8,%9}, {%0,%1,%2,%3};"
        : "+f"(c[0]), "+f"(c[1]), "+f"(c[2]), "+f"(c[3])
        : "r"(a0), "r"(a1), "r"(a2), "r"(a3), "r"(b0), "r"(b1));
}

// ---------------------------------------------------------------------------
// Persistent mega-kernel: Phase A (convert + argmax) | barrier |
//                         Phase B (gram + rdist)     | barrier |
//                         Phase C (min-ratio)
// ---------------------------------------------------------------------------
__global__ void __launch_bounds__(256, 2)
mega_kernel(const float* __restrict__ pred, const float* __restrict__ W,
            const float* __restrict__ Kin, float* __restrict__ out) {
    __shared__ __align__(16) __nv_bfloat16 sA[2][TILE * APITCH];
    __shared__ __align__(16) __nv_bfloat16 sB[2][TILE * APITCH];
    __shared__ float sred[8];

    const int tid = threadIdx.x;
    const int wid = tid >> 5, lane = tid & 31;
    const int bid = blockIdx.x;

    // =========================== Phase A ===========================
    // 1024 units: even -> convert pair of W rows, odd -> argmax 8 pred rows.
    for (int u = bid; u < 1024; u += GRIDN) {
        if (!(u & 1)) {
            // convert unit: rows 2c, 2c+1 (half-block each)
            int c2 = u >> 1;
            int half = tid >> 7;
            int wg_tid = tid & 127;
            int row = c2 * 2 + half;
            float s = 0.f;
            if (row < NC) {
                const float4* src = (const float4*)(W + (long)row * ND);
                uint2* dst = (uint2*)(g_Wbf + (long)row * ND);
                float4 v[4];
                #pragma unroll
                for (int it = 0; it < 4; it++) v[it] = src[it * 128 + wg_tid];
                #pragma unroll
                for (int it = 0; it < 4; it++) {
                    union { uint2 uu; __nv_bfloat16 h[4]; } pk;
                    pk.h[0] = __float2bfloat16_rn(v[it].x);
                    pk.h[1] = __float2bfloat16_rn(v[it].y);
                    pk.h[2] = __float2bfloat16_rn(v[it].z);
                    pk.h[3] = __float2bfloat16_rn(v[it].w);
                    #pragma unroll
                    for (int i = 0; i < 4; i++) {
                        float f = __bfloat162float(pk.h[i]);
                        s += f * f;
                    }
                    dst[it * 128 + wg_tid] = pk.uu;
                }
            } else {
                uint2* dst = (uint2*)(g_Wbf + (long)row * ND);
                #pragma unroll
                for (int it = 0; it < 4; it++) dst[it * 128 + wg_tid] = make_uint2(0, 0);
            }
            for (int o = 16; o > 0; o >>= 1) s += __shfl_down_sync(0xFFFFFFFFu, s, o);
            if (lane == 0) sred[wid] = s;
            __syncthreads();
            if (wg_tid == 0) {
                g_sq[row] = sred[half * 4] + sred[half * 4 + 1] +
                            sred[half * 4 + 2] + sred[half * 4 + 3];
            }
            __syncthreads();   // protect sred before next unit
        } else {
            // argmax unit: warp-per-row, 8 rows
            int b = (u >> 1) * 8 + wid;
            const float4* pr = (const float4*)(pred + (long)b * NC);
            float best = -CUDART_INF_F;
            int bidx = NC;
            #pragma unroll
            for (int it = 0; it < 8; it++) {
                int idx = it * 32 + lane;
                if (idx < 250) {
                    float4 v = pr[idx];
                    int c = idx * 4;
                    if (v.x > best) { best = v.x; bidx = c; }
                    if (v.y > best) { best = v.y; bidx = c + 1; }
                    if (v.z > best) { best = v.z; bidx = c + 2; }
                    if (v.w > best) { best = v.w; bidx = c + 3; }
                }
            }
            #pragma unroll
            for (int o = 16; o > 0; o >>= 1) {
                float v2 = __shfl_down_sync(0xFFFFFFFFu, best, o);
                int   i2 = __shfl_down_sync(0xFFFFFFFFu, bidx, o);
                if (v2 > best || (v2 == best && i2 < bidx)) { best = v2; bidx = i2; }
            }
            if (lane == 0) { g_ymax[b] = best; g_j0[b] = bidx; }
        }
    }

    grid_barrier();

    // =========================== Phase B ===========================
    if (bid < NPAIRS) {
        int p = bid;
        int ti = 0;
        while (p >= NTILE - ti) { p -= NTILE - ti; ti++; }
        int tj = ti + p;
        int rowA = ti * TILE, rowB = tj * TILE;

        int wr = wid & 3;   // 4 row-strips of 16
        int wc = wid >> 2;  // 2 col-strips of 32

        uint32_t sA0 = (uint32_t)__cvta_generic_to_shared(sA[0]);
        uint32_t sA1 = (uint32_t)__cvta_generic_to_shared(sA[1]);
        uint32_t sB0 = (uint32_t)__cvta_generic_to_shared(sB[0]);
        uint32_t sB1 = (uint32_t)__cvta_generic_to_shared(sB[1]);

        int arow = wr * 16 + (lane & 15);
        int acol = (lane >> 4) << 3;
        uint32_t aOff = (uint32_t)(arow * APITCH + acol) * 2u;
        int brow = wc * 32 + (lane & 7) + ((lane >> 4) << 3);
        int bcol = ((lane >> 3) & 1) << 3;
        uint32_t bOff = (uint32_t)(brow * APITCH + bcol) * 2u;

        int ldg_tile[4], ldg_row[4], ldg_sub[4];
        #pragma unroll
        for (int t = 0; t < 4; t++) {
            ldg_tile[t] = t >> 1;
            ldg_row[t]  = ((t & 1) << 5) + (tid >> 3);
            ldg_sub[t]  = tid & 7;
        }

        float acc[4][4] = {};
        uint4 fetch[4];

        #pragma unroll
        for (int t = 0; t < 4; t++) {
            const __nv_bfloat16* gp = g_Wbf +
                (long)((ldg_tile[t] ? rowB : rowA) + ldg_row[t]) * ND + ldg_sub[t] * 8;
            fetch[t] = *(const uint4*)gp;
        }
        #pragma unroll
        for (int t = 0; t < 4; t++) {
            __nv_bfloat16* dp = (ldg_tile[t] ? sB[0] : sA[0]) + ldg_row[t] * APITCH + ldg_sub[t] * 8;
            *(uint4*)dp = fetch[t];
        }
        __syncthreads();

        const int NSTAGE = ND / KC;  // 32
        for (int s = 0; s < NSTAGE; s++) {
            if (s + 1 < NSTAGE) {
                int k0 = (s + 1) * KC;
                #pragma unroll
                for (int t = 0; t < 4; t++) {
                    const __nv_bfloat16* gp = g_Wbf +
                        (long)((ldg_tile[t] ? rowB : rowA) + ldg_row[t]) * ND + k0 + ldg_sub[t] * 8;
                    fetch[t] = *(const uint4*)gp;
                }
            }

            int buf = s & 1;
            uint32_t aBase  = (buf ? sA1 : sA0) + aOff;
            uint32_t bBase0 = (buf ? sB1 : sB0) + bOff;
            uint32_t bBase1 = bBase0 + 16 * APITCH * 2;

            #pragma unroll
            for (int kk = 0; kk < 4; kk++) {
                uint32_t a0, a1, a2, a3;
                ldsm_x4(a0, a1, a2, a3, aBase + kk * 32);
                uint32_t b0, b1, b2, b3, b4, b5, b6, b7;
                ldsm_x4(b0, b1, b2, b3, bBase0 + kk * 32);
                ldsm_x4(b4, b5, b6, b7, bBase1 + kk * 32);
                mma16816(acc[0], a0, a1, a2, a3, b0, b1);
                mma16816(acc[1], a0, a1, a2, a3, b2, b3);
                mma16816(acc[2], a0, a1, a2, a3, b4, b5);
                mma16816(acc[3], a0, a1, a2, a3, b6, b7);
            }

            if (s + 1 < NSTAGE) {
                int nbuf = (s + 1) & 1;
                #pragma unroll
                for (int t = 0; t < 4; t++) {
                    __nv_bfloat16* dp = (ldg_tile[t] ? sB[nbuf] : sA[nbuf]) +
                                        ldg_row[t] * APITCH + ldg_sub[t] * 8;
                    *(uint4*)dp = fetch[t];
                }
            }
            __syncthreads();
        }

        const float DS = (float)(1.0 / (double)0.224f);
        float invk = 1.0f / (Kin[0] * DS);

        int g = lane >> 2, tg = lane & 3;
        int gi0 = rowA + wr * 16 + g;
        int gi1 = gi0 + 8;
        float sqi0 = g_sq[gi0], sqi1 = g_sq[gi1];

        #pragma unroll
        for (int t = 0; t < 4; t++) {
            int gj = rowB + wc * 32 + t * 8 + tg * 2;
            float sqj0 = g_sq[gj], sqj1 = g_sq[gj + 1];
            float d2, rv;
            d2 = sqi0 + sqj0 - 2.f * acc[t][0];
            rv = rsqrtf(fmaxf(d2, 0.f)) * invk;
            g_rdist[gi0 * CP + gj] = rv;  g_rdist[gj * CP + gi0] = rv;
            d2 = sqi0 + sqj1 - 2.f * acc[t][1];
            rv = rsqrtf(fmaxf(d2, 0.f)) * invk;
            g_rdist[gi0 * CP + gj + 1] = rv;  g_rdist[(gj + 1) * CP + gi0] = rv;
            d2 = sqi1 + sqj0 - 2.f * acc[t][2];
            rv = rsqrtf(fmaxf(d2, 0.f)) * invk;
            g_rdist[gi1 * CP + gj] = rv;  g_rdist[gj * CP + gi1] = rv;
            d2 = sqi1 + sqj1 - 2.f * acc[t][3];
            rv = rsqrtf(fmaxf(d2, 0.f)) * invk;
            g_rdist[gi1 * CP + gj + 1] = rv;  g_rdist[(gj + 1) * CP + gi1] = rv;
        }
    }

    grid_barrier();

    // =========================== Phase C ===========================
    // warp-per-row min; pred + rdist are L2-hot from earlier phases.
    for (int u = bid; u < NB / 8; u += GRIDN) {
        int b = u * 8 + wid;
        int j0 = g_j0[b];
        float ym = g_ymax[b];
        const float4* pr = (const float4*)(pred + (long)b * NC);
        const float4* dr = (const float4*)(g_rdist + (long)j0 * CP);

        float mn = CUDART_INF_F;
        #pragma unroll
        for (int it = 0; it < 8; it++) {
            int idx = it * 32 + lane;
            if (idx < 250) {
                float4 pv = pr[idx];
                float4 dv = dr[idx];
                int c = idx * 4;
                float r0 = (c     == j0) ? CUDART_INF_F : (ym - pv.x) * dv.x;
                float r1 = (c + 1 == j0) ? CUDART_INF_F : (ym - pv.y) * dv.y;
                float r2 = (c + 2 == j0) ? CUDART_INF_F : (ym - pv.z) * dv.z;
                float r3 = (c + 3 == j0) ? CUDART_INF_F : (ym - pv.w) * dv.w;
                mn = fminf(mn, fminf(fminf(r0, r1), fminf(r2, r3)));
            }
        }
        #pragma unroll
        for (int o = 16; o > 0; o >>= 1)
            mn = fminf(mn, __shfl_down_sync(0xFFFFFFFFu, mn, o));
        if (lane == 0) out[b] = mn;
    }
}

// ---------------------------------------------------------------------------
extern "C" void kernel_launch(void* const* d_in, const int* in_sizes, int n_in,
                              void* d_out, int out_size) {
    const float* pred = (const float*)d_in[0];
    const float* W    = (const float*)d_in[1];
    const float* K    = (const float*)d_in[2];
    float* out = (float*)d_out;

    mega_kernel<<<GRIDN, 256>>>(pred, W, K, out);
}